// round 8
// baseline (speedup 1.0000x reference)
#include <cuda_runtime.h>

#define BATCH 4096
#define DIM   4096
#define MARGIN 0.5f

// Scratch (allocation-free rule: __device__ globals).
__device__ float        g_partial[BATCH];
__device__ unsigned int g_count;   // zero-init at module load; reset by last CTA

// ---------------------------------------------------------------------------
// Fused kernel, release-only arrival:
//  - partial written with STG.CG (L1-bypass -> L2, globally visible)
//  - arrive with atom.RELEASE.gpu (orders the stcg; NO acquire -> no per-CTA
//    L1 invalidation, which is what sank R2 [fence] and R6 [acq_rel])
//  - only the single last-arriving CTA issues one fence.acq_rel.gpu, then
//    propagates to its threads via __syncthreads
//  - last CTA reduces all 4096 partials in fixed order (deterministic)
// ---------------------------------------------------------------------------
__global__ __launch_bounds__(256, 8)
void triplet_fused_kernel(const float* __restrict__ f,
                          const float* __restrict__ label,
                          const int*   __restrict__ idx1,
                          const int*   __restrict__ idx2,
                          float*       __restrict__ out)
{
    const int i = blockIdx.x;
    const int t = threadIdx.x;

    const int j1 = __ldg(&idx1[i]);
    const int j2 = __ldg(&idx2[i]);

    const float4* __restrict__ a  = (const float4*)(f + (size_t)i  * DIM);
    const float4* __restrict__ b1 = (const float4*)(f + (size_t)j1 * DIM);
    const float4* __restrict__ b2 = (const float4*)(f + (size_t)j2 * DIM);

    float s1 = 0.0f, s2 = 0.0f;

    #pragma unroll
    for (int k = 0; k < 4; k++) {
        const int idx = t + k * 256;
        const float4 av = __ldg(&a[idx]);
        const float4 v1 = __ldg(&b1[idx]);
        const float4 v2 = __ldg(&b2[idx]);
        float d;
        d = av.x - v1.x; s1 = fmaf(d, d, s1);
        d = av.y - v1.y; s1 = fmaf(d, d, s1);
        d = av.z - v1.z; s1 = fmaf(d, d, s1);
        d = av.w - v1.w; s1 = fmaf(d, d, s1);
        d = av.x - v2.x; s2 = fmaf(d, d, s2);
        d = av.y - v2.y; s2 = fmaf(d, d, s2);
        d = av.z - v2.z; s2 = fmaf(d, d, s2);
        d = av.w - v2.w; s2 = fmaf(d, d, s2);
    }

    #pragma unroll
    for (int off = 16; off > 0; off >>= 1) {
        s1 += __shfl_down_sync(0xFFFFFFFFu, s1, off);
        s2 += __shfl_down_sync(0xFFFFFFFFu, s2, off);
    }

    __shared__ float sh1[8], sh2[8];
    __shared__ int   last_flag;
    const int wid = t >> 5;
    const int lid = t & 31;
    if (lid == 0) { sh1[wid] = s1; sh2[wid] = s2; }
    __syncthreads();

    if (t == 0) {
        float t1 = 0.0f, t2 = 0.0f;
        #pragma unroll
        for (int w = 0; w < 8; w++) { t1 += sh1[w]; t2 += sh2[w]; }

        const float l  = __ldg(&label[i]);
        const float l1 = __ldg(&label[j1]);
        const float l2 = __ldg(&label[j2]);
        const float d1 = fabsf(l - l1);
        const float d2 = fabsf(l - l2);
        const bool cond = (d1 >= d2);       // true -> idx2 is the near sample

        const float a2n    = cond ? t2 : t1;
        const float a2f    = cond ? t1 : t2;
        const float near_l = cond ? l2 : l1;
        const float far_l  = cond ? l1 : l2;

        const float dn = l - near_l;
        const float df = l - far_l;
        const float alpha = df * df - dn * dn;

        // L1-bypass store: partial lands in L2, globally visible.
        __stcg(&g_partial[i], fmaxf(a2n - a2f + alpha * MARGIN, 0.0f));

        // RELEASE-only arrive: orders the stcg; no acquire, no L1 invalidate.
        unsigned int prev;
        asm volatile("atom.release.gpu.add.u32 %0, [%1], %2;"
                     : "=r"(prev) : "l"(&g_count), "r"(1u) : "memory");

        if (prev == (unsigned int)(BATCH - 1)) {
            // Single acquire upgrade for the one last CTA only.
            asm volatile("fence.acq_rel.gpu;" ::: "memory");
            last_flag = 1;
        } else {
            last_flag = 0;
        }
    }
    __syncthreads();   // propagates t0's acquire to the whole CTA

    // Last CTA: deterministic fixed-order reduction (ldcg = read from L2).
    if (last_flag) {
        const float4* p = (const float4*)g_partial;   // 1024 float4
        const float4 v0 = __ldcg(&p[t]);
        const float4 v1 = __ldcg(&p[t + 256]);
        const float4 v2 = __ldcg(&p[t + 512]);
        const float4 v3 = __ldcg(&p[t + 768]);

        float s = (((v0.x + v0.y) + (v0.z + v0.w))
                +  ((v1.x + v1.y) + (v1.z + v1.w)))
                + (((v2.x + v2.y) + (v2.z + v2.w))
                +  ((v3.x + v3.y) + (v3.z + v3.w)));

        #pragma unroll
        for (int off = 16; off > 0; off >>= 1)
            s += __shfl_down_sync(0xFFFFFFFFu, s, off);

        __shared__ float shr[8];
        if (lid == 0) shr[wid] = s;
        __syncthreads();

        if (t == 0) {
            float tot = ((shr[0] + shr[1]) + (shr[2] + shr[3]))
                      + ((shr[4] + shr[5]) + (shr[6] + shr[7]));
            out[0] = tot;
            __stcg(&g_count, 0u);   // reset for next graph replay
        }
    }
}

extern "C" void kernel_launch(void* const* d_in, const int* in_sizes, int n_in,
                              void* d_out, int out_size)
{
    const float* f     = (const float*)d_in[0];
    const float* label = (const float*)d_in[1];
    const int*   idx1  = (const int*)d_in[2];
    const int*   idx2  = (const int*)d_in[3];
    float* out = (float*)d_out;

    triplet_fused_kernel<<<BATCH, 256>>>(f, label, idx1, idx2, out);
}

// round 9
// speedup vs baseline: 1.1565x; 1.1565x over previous
#include <cuda_runtime.h>

#define BATCH 4096
#define DIM   4096
#define MARGIN 0.5f
#define ROWS_PER_CTA 4
#define GRID (BATCH / ROWS_PER_CTA)   // 1024 CTAs -> single wave at occ 8

// Scratch (allocation-free rule: __device__ globals).
__device__ float        g_partial[GRID];
__device__ unsigned int g_count;   // zero-init at load; reset by last CTA

// ---------------------------------------------------------------------------
// Persistent fused kernel: 1024 CTAs x 4 rows. Per row: both gathered
// squared-L2 distances with the proven 32-reg float4 loop; per-warp sums
// parked in smem. ONE barrier, then t0 computes all 4 hinges, accumulates a
// single per-CTA partial (fixed order), stcg + release-arrive. Last CTA
// (single acquire fence) reduces 1024 partials in fixed order.
// ---------------------------------------------------------------------------
__global__ __launch_bounds__(256, 8)
void triplet_fused_kernel(const float* __restrict__ f,
                          const float* __restrict__ label,
                          const int*   __restrict__ idx1,
                          const int*   __restrict__ idx2,
                          float*       __restrict__ out)
{
    const int cta = blockIdx.x;
    const int t   = threadIdx.x;
    const int wid = t >> 5;
    const int lid = t & 31;

    __shared__ float sh1[ROWS_PER_CTA][8];
    __shared__ float sh2[ROWS_PER_CTA][8];
    __shared__ int   last_flag;

    #pragma unroll
    for (int r = 0; r < ROWS_PER_CTA; r++) {
        const int i  = cta * ROWS_PER_CTA + r;
        const int j1 = __ldg(&idx1[i]);
        const int j2 = __ldg(&idx2[i]);

        const float4* __restrict__ a  = (const float4*)(f + (size_t)i  * DIM);
        const float4* __restrict__ b1 = (const float4*)(f + (size_t)j1 * DIM);
        const float4* __restrict__ b2 = (const float4*)(f + (size_t)j2 * DIM);

        float s1 = 0.0f, s2 = 0.0f;

        #pragma unroll
        for (int k = 0; k < 4; k++) {
            const int idx = t + k * 256;
            const float4 av = __ldg(&a[idx]);
            const float4 v1 = __ldg(&b1[idx]);
            const float4 v2 = __ldg(&b2[idx]);
            float d;
            d = av.x - v1.x; s1 = fmaf(d, d, s1);
            d = av.y - v1.y; s1 = fmaf(d, d, s1);
            d = av.z - v1.z; s1 = fmaf(d, d, s1);
            d = av.w - v1.w; s1 = fmaf(d, d, s1);
            d = av.x - v2.x; s2 = fmaf(d, d, s2);
            d = av.y - v2.y; s2 = fmaf(d, d, s2);
            d = av.z - v2.z; s2 = fmaf(d, d, s2);
            d = av.w - v2.w; s2 = fmaf(d, d, s2);
        }

        #pragma unroll
        for (int off = 16; off > 0; off >>= 1) {
            s1 += __shfl_down_sync(0xFFFFFFFFu, s1, off);
            s2 += __shfl_down_sync(0xFFFFFFFFu, s2, off);
        }
        if (lid == 0) { sh1[r][wid] = s1; sh2[r][wid] = s2; }
    }
    __syncthreads();   // single barrier for all 4 rows' partials

    if (t == 0) {
        float local = 0.0f;
        #pragma unroll
        for (int r = 0; r < ROWS_PER_CTA; r++) {
            float t1 = 0.0f, t2 = 0.0f;
            #pragma unroll
            for (int w = 0; w < 8; w++) { t1 += sh1[r][w]; t2 += sh2[r][w]; }

            const int i  = cta * ROWS_PER_CTA + r;
            const int j1 = __ldg(&idx1[i]);
            const int j2 = __ldg(&idx2[i]);
            const float l  = __ldg(&label[i]);
            const float l1 = __ldg(&label[j1]);
            const float l2 = __ldg(&label[j2]);
            const float d1 = fabsf(l - l1);
            const float d2 = fabsf(l - l2);
            const bool cond = (d1 >= d2);   // true -> idx2 is the near sample

            const float a2n    = cond ? t2 : t1;
            const float a2f    = cond ? t1 : t2;
            const float near_l = cond ? l2 : l1;
            const float far_l  = cond ? l1 : l2;

            const float dn = l - near_l;
            const float df = l - far_l;
            const float alpha = df * df - dn * dn;
            local += fmaxf(a2n - a2f + alpha * MARGIN, 0.0f);
        }

        // L1-bypass store: per-CTA partial lands in L2, globally visible.
        __stcg(&g_partial[cta], local);

        // RELEASE-only arrive (orders the stcg); no per-CTA L1 invalidate.
        unsigned int prev;
        asm volatile("atom.release.gpu.add.u32 %0, [%1], %2;"
                     : "=r"(prev) : "l"(&g_count), "r"(1u) : "memory");

        if (prev == (unsigned int)(GRID - 1)) {
            asm volatile("fence.acq_rel.gpu;" ::: "memory");  // single acquire
            last_flag = 1;
        } else {
            last_flag = 0;
        }
    }
    __syncthreads();

    // Last CTA: deterministic fixed-order reduction of 1024 partials.
    if (last_flag) {
        const float4* p = (const float4*)g_partial;   // 256 float4
        const float4 v = __ldcg(&p[t]);
        float s = (v.x + v.y) + (v.z + v.w);

        #pragma unroll
        for (int off = 16; off > 0; off >>= 1)
            s += __shfl_down_sync(0xFFFFFFFFu, s, off);

        __shared__ float shr[8];
        if (lid == 0) shr[wid] = s;
        __syncthreads();

        if (t == 0) {
            float tot = ((shr[0] + shr[1]) + (shr[2] + shr[3]))
                      + ((shr[4] + shr[5]) + (shr[6] + shr[7]));
            out[0] = tot;
            __stcg(&g_count, 0u);   // reset for next graph replay
        }
    }
}

extern "C" void kernel_launch(void* const* d_in, const int* in_sizes, int n_in,
                              void* d_out, int out_size)
{
    const float* f     = (const float*)d_in[0];
    const float* label = (const float*)d_in[1];
    const int*   idx1  = (const int*)d_in[2];
    const int*   idx2  = (const int*)d_in[3];
    float* out = (float*)d_out;

    triplet_fused_kernel<<<GRID, 256>>>(f, label, idx1, idx2, out);
}

// round 10
// speedup vs baseline: 1.2062x; 1.0430x over previous
#include <cuda_runtime.h>

#define BATCH 4096
#define DIM   4096
#define MARGIN 0.5f

// scratch for per-row hinge losses (allocation-free rule: __device__ global)
__device__ float g_partial[BATCH];

// ---------------------------------------------------------------------------
// Kernel 1: one CTA per row (proven fastest mainloop: regs=32, occ~89%).
// Partials stored with STG.CG (straight to L2). Each CTA signals PDL
// launch_dependents after its store so the reduce kernel's launch overhead
// overlaps the tail wave.
// ---------------------------------------------------------------------------
__global__ __launch_bounds__(256, 8)
void triplet_rows_kernel(const float* __restrict__ f,
                         const float* __restrict__ label,
                         const int*   __restrict__ idx1,
                         const int*   __restrict__ idx2)
{
    const int i = blockIdx.x;
    const int t = threadIdx.x;

    const int j1 = __ldg(&idx1[i]);
    const int j2 = __ldg(&idx2[i]);

    const float4* __restrict__ a  = (const float4*)(f + (size_t)i  * DIM);
    const float4* __restrict__ b1 = (const float4*)(f + (size_t)j1 * DIM);
    const float4* __restrict__ b2 = (const float4*)(f + (size_t)j2 * DIM);

    float s1 = 0.0f, s2 = 0.0f;

    #pragma unroll
    for (int k = 0; k < 4; k++) {
        const int idx = t + k * 256;
        const float4 av = __ldg(&a[idx]);
        const float4 v1 = __ldg(&b1[idx]);
        const float4 v2 = __ldg(&b2[idx]);
        float d;
        d = av.x - v1.x; s1 = fmaf(d, d, s1);
        d = av.y - v1.y; s1 = fmaf(d, d, s1);
        d = av.z - v1.z; s1 = fmaf(d, d, s1);
        d = av.w - v1.w; s1 = fmaf(d, d, s1);
        d = av.x - v2.x; s2 = fmaf(d, d, s2);
        d = av.y - v2.y; s2 = fmaf(d, d, s2);
        d = av.z - v2.z; s2 = fmaf(d, d, s2);
        d = av.w - v2.w; s2 = fmaf(d, d, s2);
    }

    #pragma unroll
    for (int off = 16; off > 0; off >>= 1) {
        s1 += __shfl_down_sync(0xFFFFFFFFu, s1, off);
        s2 += __shfl_down_sync(0xFFFFFFFFu, s2, off);
    }

    __shared__ float sh1[8], sh2[8];
    const int wid = t >> 5;
    const int lid = t & 31;
    if (lid == 0) { sh1[wid] = s1; sh2[wid] = s2; }
    __syncthreads();

    if (t == 0) {
        float t1 = 0.0f, t2 = 0.0f;
        #pragma unroll
        for (int w = 0; w < 8; w++) { t1 += sh1[w]; t2 += sh2[w]; }

        const float l  = __ldg(&label[i]);
        const float l1 = __ldg(&label[j1]);
        const float l2 = __ldg(&label[j2]);
        const float d1 = fabsf(l - l1);
        const float d2 = fabsf(l - l2);
        const bool cond = (d1 >= d2);       // true -> idx2 is the near sample

        const float a2n    = cond ? t2 : t1;
        const float a2f    = cond ? t1 : t2;
        const float near_l = cond ? l2 : l1;
        const float far_l  = cond ? l1 : l2;

        const float dn = l - near_l;
        const float df = l - far_l;
        const float alpha = df * df - dn * dn;
        __stcg(&g_partial[i], fmaxf(a2n - a2f + alpha * MARGIN, 0.0f));
    }

    // Allow the dependent (reduce) kernel to begin launching now; its
    // griddepcontrol.wait still blocks until this grid fully completes+flushes.
    asm volatile("griddepcontrol.launch_dependents;");
}

// ---------------------------------------------------------------------------
// Kernel 2: PDL-launched reduce. Waits for predecessor completion (flush),
// then deterministic fixed-order sum of 4096 partials via L2 (ldcg).
// ---------------------------------------------------------------------------
__global__ __launch_bounds__(128, 1)
void reduce_kernel(float* __restrict__ out)
{
    // Block until the preceding grid's memory is visible.
    asm volatile("griddepcontrol.wait;");

    const int t = threadIdx.x;
    const float4* p = (const float4*)g_partial;  // 1024 float4

    const float4 v0 = __ldcg(&p[t]);
    const float4 v1 = __ldcg(&p[t + 128]);
    const float4 v2 = __ldcg(&p[t + 256]);
    const float4 v3 = __ldcg(&p[t + 384]);
    const float4 v4 = __ldcg(&p[t + 512]);
    const float4 v5 = __ldcg(&p[t + 640]);
    const float4 v6 = __ldcg(&p[t + 768]);
    const float4 v7 = __ldcg(&p[t + 896]);

    float s = (((v0.x + v0.y) + (v0.z + v0.w))
            +  ((v1.x + v1.y) + (v1.z + v1.w)))
            + (((v2.x + v2.y) + (v2.z + v2.w))
            +  ((v3.x + v3.y) + (v3.z + v3.w)))
            + (((v4.x + v4.y) + (v4.z + v4.w))
            +  ((v5.x + v5.y) + (v5.z + v5.w)))
            + (((v6.x + v6.y) + (v6.z + v6.w))
            +  ((v7.x + v7.y) + (v7.z + v7.w)));

    #pragma unroll
    for (int off = 16; off > 0; off >>= 1)
        s += __shfl_down_sync(0xFFFFFFFFu, s, off);

    __shared__ float sh[4];
    const int wid = t >> 5;
    const int lid = t & 31;
    if (lid == 0) sh[wid] = s;
    __syncthreads();

    if (t == 0)
        out[0] = (sh[0] + sh[1]) + (sh[2] + sh[3]);
}

extern "C" void kernel_launch(void* const* d_in, const int* in_sizes, int n_in,
                              void* d_out, int out_size)
{
    const float* f     = (const float*)d_in[0];
    const float* label = (const float*)d_in[1];
    const int*   idx1  = (const int*)d_in[2];
    const int*   idx2  = (const int*)d_in[3];
    float* out = (float*)d_out;

    triplet_rows_kernel<<<BATCH, 256>>>(f, label, idx1, idx2);

    // Reduce kernel with Programmatic Dependent Launch: its launch overhead
    // overlaps the main kernel's tail wave.
    cudaLaunchConfig_t cfg = {};
    cfg.gridDim  = dim3(1, 1, 1);
    cfg.blockDim = dim3(128, 1, 1);
    cfg.dynamicSmemBytes = 0;
    cudaLaunchAttribute attr[1];
    attr[0].id = cudaLaunchAttributeProgrammaticStreamSerialization;
    attr[0].val.programmaticStreamSerializationAllowed = 1;
    cfg.attrs = attr;
    cfg.numAttrs = 1;
    cudaLaunchKernelEx(&cfg, reduce_kernel, out);
}

// round 11
// speedup vs baseline: 1.2124x; 1.0052x over previous
#include <cuda_runtime.h>

#define BATCH 4096
#define DIM   4096
#define MARGIN 0.5f
#define GRID  1184   // 148 SMs x 8 CTAs -> exactly one wave, persistent

// scratch for per-row hinge losses (allocation-free rule: __device__ global)
__device__ float g_partial[BATCH];

// ---------------------------------------------------------------------------
// Kernel 1: persistent single-wave grid. Each CTA handles rows
// cta, cta+GRID, ... (3-4 rows) with the proven 32-reg float4 inner loop.
// No wave transitions; tail raggedness limited to one row-iteration.
// Partials go straight to L2 (stcg); PDL signal at the end.
// ---------------------------------------------------------------------------
__global__ __launch_bounds__(256, 8)
void triplet_rows_kernel(const float* __restrict__ f,
                         const float* __restrict__ label,
                         const int*   __restrict__ idx1,
                         const int*   __restrict__ idx2)
{
    const int t   = threadIdx.x;
    const int wid = t >> 5;
    const int lid = t & 31;

    __shared__ float sh1[8], sh2[8];

    for (int i = blockIdx.x; i < BATCH; i += GRID) {
        const int j1 = __ldg(&idx1[i]);
        const int j2 = __ldg(&idx2[i]);

        const float4* __restrict__ a  = (const float4*)(f + (size_t)i  * DIM);
        const float4* __restrict__ b1 = (const float4*)(f + (size_t)j1 * DIM);
        const float4* __restrict__ b2 = (const float4*)(f + (size_t)j2 * DIM);

        float s1 = 0.0f, s2 = 0.0f;

        #pragma unroll
        for (int k = 0; k < 4; k++) {
            const int idx = t + k * 256;
            const float4 av = __ldg(&a[idx]);
            const float4 v1 = __ldg(&b1[idx]);
            const float4 v2 = __ldg(&b2[idx]);
            float d;
            d = av.x - v1.x; s1 = fmaf(d, d, s1);
            d = av.y - v1.y; s1 = fmaf(d, d, s1);
            d = av.z - v1.z; s1 = fmaf(d, d, s1);
            d = av.w - v1.w; s1 = fmaf(d, d, s1);
            d = av.x - v2.x; s2 = fmaf(d, d, s2);
            d = av.y - v2.y; s2 = fmaf(d, d, s2);
            d = av.z - v2.z; s2 = fmaf(d, d, s2);
            d = av.w - v2.w; s2 = fmaf(d, d, s2);
        }

        #pragma unroll
        for (int off = 16; off > 0; off >>= 1) {
            s1 += __shfl_down_sync(0xFFFFFFFFu, s1, off);
            s2 += __shfl_down_sync(0xFFFFFFFFu, s2, off);
        }

        if (lid == 0) { sh1[wid] = s1; sh2[wid] = s2; }
        __syncthreads();

        if (t == 0) {
            float t1 = 0.0f, t2 = 0.0f;
            #pragma unroll
            for (int w = 0; w < 8; w++) { t1 += sh1[w]; t2 += sh2[w]; }

            const float l  = __ldg(&label[i]);
            const float l1 = __ldg(&label[j1]);
            const float l2 = __ldg(&label[j2]);
            const float d1 = fabsf(l - l1);
            const float d2 = fabsf(l - l2);
            const bool cond = (d1 >= d2);   // true -> idx2 is the near sample

            const float a2n    = cond ? t2 : t1;
            const float a2f    = cond ? t1 : t2;
            const float near_l = cond ? l2 : l1;
            const float far_l  = cond ? l1 : l2;

            const float dn = l - near_l;
            const float df = l - far_l;
            const float alpha = df * df - dn * dn;
            __stcg(&g_partial[i], fmaxf(a2n - a2f + alpha * MARGIN, 0.0f));
        }
        __syncthreads();   // protect sh1/sh2 reuse across row iterations
    }

    // Let the dependent reduce start its launch; its griddepcontrol.wait
    // still blocks until this grid fully completes + flushes.
    asm volatile("griddepcontrol.launch_dependents;");
}

// ---------------------------------------------------------------------------
// Kernel 2: PDL-launched reduce (unchanged). Deterministic fixed-order sum.
// ---------------------------------------------------------------------------
__global__ __launch_bounds__(128, 1)
void reduce_kernel(float* __restrict__ out)
{
    asm volatile("griddepcontrol.wait;");

    const int t = threadIdx.x;
    const float4* p = (const float4*)g_partial;  // 1024 float4

    const float4 v0 = __ldcg(&p[t]);
    const float4 v1 = __ldcg(&p[t + 128]);
    const float4 v2 = __ldcg(&p[t + 256]);
    const float4 v3 = __ldcg(&p[t + 384]);
    const float4 v4 = __ldcg(&p[t + 512]);
    const float4 v5 = __ldcg(&p[t + 640]);
    const float4 v6 = __ldcg(&p[t + 768]);
    const float4 v7 = __ldcg(&p[t + 896]);

    float s = (((v0.x + v0.y) + (v0.z + v0.w))
            +  ((v1.x + v1.y) + (v1.z + v1.w)))
            + (((v2.x + v2.y) + (v2.z + v2.w))
            +  ((v3.x + v3.y) + (v3.z + v3.w)))
            + (((v4.x + v4.y) + (v4.z + v4.w))
            +  ((v5.x + v5.y) + (v5.z + v5.w)))
            + (((v6.x + v6.y) + (v6.z + v6.w))
            +  ((v7.x + v7.y) + (v7.z + v7.w)));

    #pragma unroll
    for (int off = 16; off > 0; off >>= 1)
        s += __shfl_down_sync(0xFFFFFFFFu, s, off);

    __shared__ float sh[4];
    const int wid = t >> 5;
    const int lid = t & 31;
    if (lid == 0) sh[wid] = s;
    __syncthreads();

    if (t == 0)
        out[0] = (sh[0] + sh[1]) + (sh[2] + sh[3]);
}

extern "C" void kernel_launch(void* const* d_in, const int* in_sizes, int n_in,
                              void* d_out, int out_size)
{
    const float* f     = (const float*)d_in[0];
    const float* label = (const float*)d_in[1];
    const int*   idx1  = (const int*)d_in[2];
    const int*   idx2  = (const int*)d_in[3];
    float* out = (float*)d_out;

    triplet_rows_kernel<<<GRID, 256>>>(f, label, idx1, idx2);

    cudaLaunchConfig_t cfg = {};
    cfg.gridDim  = dim3(1, 1, 1);
    cfg.blockDim = dim3(128, 1, 1);
    cfg.dynamicSmemBytes = 0;
    cudaLaunchAttribute attr[1];
    attr[0].id = cudaLaunchAttributeProgrammaticStreamSerialization;
    attr[0].val.programmaticStreamSerializationAllowed = 1;
    cfg.attrs = attr;
    cfg.numAttrs = 1;
    cudaLaunchKernelEx(&cfg, reduce_kernel, out);
}